// round 13
// baseline (speedup 1.0000x reference)
#include <cuda_runtime.h>
#include <cuda_bf16.h>
#include <math.h>

#define S_WORDS 2048
#define LMAX    16
#define CE      256
#define WE      512
#define HDIM    1024
#define GC      (4*CE)     // 1024 gate rows, char LSTM
#define KW      (WE+CE)    // 768  (we | char_feat)
#define ALPHA   256
#define NBLK_WL 128        // persistent blocks for word LSTM (<= 148 SMs)
#define CWPB    16         // words per block, char LSTM

// ---------------- device scratch (no allocations allowed) ----------------
__device__ float g_WcT[2*CE*GC];      // [k=512][g=1024]; rows 0..255 = Wih_c^T, 256.. = Whh_c^T
__device__ float g_CG[ALPHA*GC];      // per-char x-gate table: emb@Wih^T + bias
__device__ float g_lasth[S_WORDS*CE]; // char-LSTM output feature per word
// tagged h broadcast: high 32 bits = step tag, low 32 bits = h bits. Double-buffered.
__device__ unsigned long long g_hpair[2*HDIM];

__device__ __forceinline__ float sigf(float x) { return 1.f / (1.f + __expf(-x)); }

// ---------------- prep: char weights transpose, CG table, tag reset ----------------
__global__ void prep_c(const float* __restrict__ Wih_c, const float* __restrict__ Whh_c) {
    int idx = blockIdx.x * blockDim.x + threadIdx.x;
    if (idx >= 2 * CE * GC) return;
    int k = idx / GC, g = idx % GC;
    g_WcT[idx] = (k < CE) ? Wih_c[g * CE + k] : Whh_c[g * CE + (k - CE)];
}

__global__ void __launch_bounds__(256) prep_cg(const float* __restrict__ char_emb,
                                               const float* __restrict__ bih_c,
                                               const float* __restrict__ bhh_c) {
    __shared__ float se[CE];
    const int ci  = blockIdx.x;
    const int tid = threadIdx.x;
    se[tid] = char_emb[ci * CE + tid];
    __syncthreads();

    float4 acc = make_float4(bih_c[4*tid+0] + bhh_c[4*tid+0],
                             bih_c[4*tid+1] + bhh_c[4*tid+1],
                             bih_c[4*tid+2] + bhh_c[4*tid+2],
                             bih_c[4*tid+3] + bhh_c[4*tid+3]);
    const float4* Wp = reinterpret_cast<const float4*>(g_WcT) + tid;   // Wih^T half
#pragma unroll 4
    for (int k = 0; k < CE; k++) {
        float4 wv = Wp[k * (GC / 4)];
        float ev = se[k];
        acc.x = fmaf(wv.x, ev, acc.x);
        acc.y = fmaf(wv.y, ev, acc.y);
        acc.z = fmaf(wv.z, ev, acc.z);
        acc.w = fmaf(wv.w, ev, acc.w);
    }
    reinterpret_cast<float4*>(g_CG + ci * GC)[tid] = acc;
}

__global__ void prep_tags() {
    int idx = blockIdx.x * blockDim.x + threadIdx.x;
    if (idx < 2 * HDIM) g_hpair[idx] = 0xFFFFFFFF00000000ull;   // tag = -1
}

// ---------------- char LSTM: 16 words/block, 512 threads (R12, unchanged) ----------------
__global__ void __launch_bounds__(512) char_lstm(
    const int*   __restrict__ char_idxs,
    const int*   __restrict__ char_lens)
{
    extern __shared__ float sm[];
    float* hh    = sm;                // CWPB*256
    float* gates = sm + CWPB * CE;    // CWPB*1024
    const int tid   = threadIdx.x;      // 0..511
    const int wbase = blockIdx.x * CWPB;
    const int unit  = tid & 255;
    const int wgrp  = (tid >> 8) * 8;

    float c[8];
    int   len[8];
#pragma unroll
    for (int j = 0; j < 8; j++) {
        int w = wgrp + j;
        c[j]   = 0.f;
        len[j] = char_lens[wbase + w];
        hh[w * CE + unit] = 0.f;
    }
    __syncthreads();

    const float2* Wp  = reinterpret_cast<const float2*>(g_WcT + (size_t)CE * GC) + tid;
    const float2* CG2 = reinterpret_cast<const float2*>(g_CG);

    for (int t = 0; t < LMAX; t++) {
        float acc[CWPB][2];
#pragma unroll
        for (int w = 0; w < CWPB; w++) {
            int ci = char_idxs[(wbase + w) * LMAX + t];
            float2 cg = CG2[ci * (GC / 2) + tid];
            acc[w][0] = cg.x; acc[w][1] = cg.y;
        }

#pragma unroll 4
        for (int k = 0; k < CE; k++) {
            float2 wv = Wp[k * (GC / 2)];
#pragma unroll
            for (int w = 0; w < CWPB; w++) {
                float xv = hh[w * CE + k];
                acc[w][0] = fmaf(wv.x, xv, acc[w][0]);
                acc[w][1] = fmaf(wv.y, xv, acc[w][1]);
            }
        }
#pragma unroll
        for (int w = 0; w < CWPB; w++)
            reinterpret_cast<float2*>(gates + w * GC)[tid] = make_float2(acc[w][0], acc[w][1]);
        __syncthreads();

#pragma unroll
        for (int j = 0; j < 8; j++) {
            int w = wgrp + j;
            float ig = gates[w * GC +          unit];
            float fg = gates[w * GC +   CE +   unit];
            float gg = gates[w * GC + 2*CE +   unit];
            float og = gates[w * GC + 3*CE +   unit];
            float cn = sigf(fg) * c[j] + sigf(ig) * tanhf(gg);
            float hn = sigf(og) * tanhf(cn);
            c[j] = cn;
            hh[w * CE + unit] = hn;
            if (t == len[j] - 1) g_lasth[(wbase + w) * CE + unit] = hn;
        }
        __syncthreads();
    }
}

// ---------------- fused word LSTM: gx-GEMM hidden under the h-poll dead time ----------------
// 128 blocks x 256 threads. Warp w of block b owns hidden unit u = 8b + w.
// Block caches its 32 Wih_w rows (row r_local = w*4+q  ->  global row q*HDIM+u) in smem.
// Per step s: (1) compute gx_{s+2} (warp w computes its own unit's 4 gates; k = lane mod 32
// partition -> conflict-free LDS; butterfly reduce -> all lanes hold sums);
// (2) stage x_{s+4} into 4-deep smem ring; poll h_{s-1} tagged pairs; BAR;
// (3) recurrence FMA + publish. Sync identical to R9/R12.
__device__ __forceinline__ void stage_x(const int* __restrict__ word_idxs,
                                        const float* __restrict__ word_emb,
                                        int t, float* dst, int tid)
{
    int wi = word_idxs[t];
#pragma unroll
    for (int j = 0; j < 3; j++) {
        int p = j * 256 + tid;
        dst[p] = (p < WE) ? word_emb[(size_t)wi * WE + p]
                          : g_lasth[(size_t)t * CE + (p - WE)];
    }
}

__device__ __forceinline__ void gemm_step(const float* __restrict__ Wsm,
                                          const float* __restrict__ xs,
                                          int t, int w, int lane,
                                          const float* bias, float* gout)
{
    const float* xv = xs + (t & 3) * KW;
    float acc0 = 0.f, acc1 = 0.f, acc2 = 0.f, acc3 = 0.f;
    const float* Wb = Wsm + (size_t)(4 * w) * KW + lane;
#pragma unroll
    for (int i = 0; i < 24; i++) {
        float x = xv[lane + 32 * i];
        acc0 = fmaf(Wb[0 * KW + 32 * i], x, acc0);
        acc1 = fmaf(Wb[1 * KW + 32 * i], x, acc1);
        acc2 = fmaf(Wb[2 * KW + 32 * i], x, acc2);
        acc3 = fmaf(Wb[3 * KW + 32 * i], x, acc3);
    }
#pragma unroll
    for (int off = 16; off > 0; off >>= 1) {
        acc0 += __shfl_xor_sync(0xffffffffu, acc0, off);
        acc1 += __shfl_xor_sync(0xffffffffu, acc1, off);
        acc2 += __shfl_xor_sync(0xffffffffu, acc2, off);
        acc3 += __shfl_xor_sync(0xffffffffu, acc3, off);
    }
    gout[0] = acc0 + bias[0];
    gout[1] = acc1 + bias[1];
    gout[2] = acc2 + bias[2];
    gout[3] = acc3 + bias[3];
}

__global__ void __launch_bounds__(256, 1) word_lstm(
    const int*   __restrict__ word_idxs,
    const float* __restrict__ word_emb,
    const float* __restrict__ Wih_w,
    const float* __restrict__ bih_w,
    const float* __restrict__ bhh_w,
    const float* __restrict__ Whh_w,
    float*       __restrict__ out)
{
    extern __shared__ float sm[];
    float* Wsm = sm;                     // 32*768
    float* hs  = sm + 32 * KW;           // 2*1024
    float* xs  = hs + 2 * HDIM;          // 4*768
    const int tid  = threadIdx.x;
    const int lane = tid & 31;
    const int w    = tid >> 5;
    const int u0   = blockIdx.x * 8;
    const int u    = u0 + w;

    // cache this block's 32 Wih_w rows in smem (coalesced, no transpose needed)
    for (int idx = tid; idx < 32 * KW; idx += 256) {
        int r = idx / KW, k = idx % KW;
        int y = r >> 2, q = r & 3;
        Wsm[idx] = Wih_w[(size_t)(q * HDIM + u0 + y) * KW + k];
    }

    float bias[4];
#pragma unroll
    for (int q = 0; q < 4; q++) bias[q] = bih_w[q * HDIM + u] + bhh_w[q * HDIM + u];

    float w0[32], w1[32], w2[32], w3[32];
#pragma unroll
    for (int i = 0; i < 32; i++) {
        w0[i] = Whh_w[(size_t)(0 * HDIM + u) * HDIM + i * 32 + lane];
        w1[i] = Whh_w[(size_t)(1 * HDIM + u) * HDIM + i * 32 + lane];
        w2[i] = Whh_w[(size_t)(2 * HDIM + u) * HDIM + i * 32 + lane];
        w3[i] = Whh_w[(size_t)(3 * HDIM + u) * HDIM + i * 32 + lane];
    }

    // prologue: stage x_0..x_3; compute gx_0, gx_1
    for (int t = 0; t < 4; t++) stage_x(word_idxs, word_emb, t, xs + t * KW, tid);
    __syncthreads();
    float gcur[4], gnext[4];
    gemm_step(Wsm, xs, 0, w, lane, bias, gcur);
    gemm_step(Wsm, xs, 1, w, lane, bias, gnext);

    float c = 0.f;

    for (int s = 0; s < S_WORDS; s++) {
        // phase 1: gx_{s+2} (hidden under the h round-trip)
        float gtmp[4];
        if (s + 2 < S_WORDS) gemm_step(Wsm, xs, s + 2, w, lane, bias, gtmp);

        // phase 2: stage x_{s+4}; poll h_{s-1}; barrier
        if (s + 4 < S_WORDS) stage_x(word_idxs, word_emb, s + 4, xs + ((s + 4) & 3) * KW, tid);

        int slot = 0;
        if (s > 0) {
            const int want = s - 1;
            slot = want & 1;
            const unsigned long long* base = g_hpair + slot * HDIM + tid;

            unsigned long long v0, v1, v2, v3;
            unsigned done = 0;
            int rounds = 0;
            do {
                if (!(done & 1u))
                    asm volatile("ld.relaxed.gpu.global.b64 %0, [%1];" : "=l"(v0) : "l"(base));
                if (!(done & 2u))
                    asm volatile("ld.relaxed.gpu.global.b64 %0, [%1];" : "=l"(v1) : "l"(base + 256));
                if (!(done & 4u))
                    asm volatile("ld.relaxed.gpu.global.b64 %0, [%1];" : "=l"(v2) : "l"(base + 512));
                if (!(done & 8u))
                    asm volatile("ld.relaxed.gpu.global.b64 %0, [%1];" : "=l"(v3) : "l"(base + 768));
                if ((int)(v0 >> 32) == want) done |= 1u;
                if ((int)(v1 >> 32) == want) done |= 2u;
                if ((int)(v2 >> 32) == want) done |= 4u;
                if ((int)(v3 >> 32) == want) done |= 8u;
                if (done == 15u) break;
                if (++rounds > 16) __nanosleep(64);   // safety valve only
            } while (true);

            hs[slot * HDIM + tid      ] = __uint_as_float((unsigned)v0);
            hs[slot * HDIM + tid + 256] = __uint_as_float((unsigned)v1);
            hs[slot * HDIM + tid + 512] = __uint_as_float((unsigned)v2);
            hs[slot * HDIM + tid + 768] = __uint_as_float((unsigned)v3);
        }
        __syncthreads();

        // phase 3: recurrence
        float a0 = 0.f, a1 = 0.f, a2 = 0.f, a3 = 0.f;
        if (s > 0) {
            const float* hrow = hs + slot * HDIM;
#pragma unroll
            for (int i = 0; i < 32; i++) {
                float hv = hrow[i * 32 + lane];
                a0 = fmaf(w0[i], hv, a0);
                a1 = fmaf(w1[i], hv, a1);
                a2 = fmaf(w2[i], hv, a2);
                a3 = fmaf(w3[i], hv, a3);
            }
#pragma unroll
            for (int off = 16; off > 0; off >>= 1) {
                a0 += __shfl_xor_sync(0xffffffffu, a0, off);
                a1 += __shfl_xor_sync(0xffffffffu, a1, off);
                a2 += __shfl_xor_sync(0xffffffffu, a2, off);
                a3 += __shfl_xor_sync(0xffffffffu, a3, off);
            }
        }

        float cn = sigf(gcur[1] + a1) * c + sigf(gcur[0] + a0) * tanhf(gcur[2] + a2);
        c = cn;
        float h = sigf(gcur[3] + a3) * tanhf(cn);

        if (lane == 0) {
            out[(size_t)s * HDIM + u] = h;
            if (s < S_WORDS - 1) {
                unsigned long long pv =
                    ((unsigned long long)(unsigned)s << 32) | (unsigned long long)__float_as_uint(h);
                const unsigned long long* ap = g_hpair + (s & 1) * HDIM + u;
                asm volatile("st.relaxed.gpu.global.b64 [%0], %1;" :: "l"(ap), "l"(pv) : "memory");
            }
        }

        // rotate the gx register ring
#pragma unroll
        for (int q = 0; q < 4; q++) { gcur[q] = gnext[q]; gnext[q] = gtmp[q]; }
    }
}

// ---------------- launch ----------------
extern "C" void kernel_launch(void* const* d_in, const int* in_sizes, int n_in,
                              void* d_out, int out_size)
{
    const int*   word_idxs = (const int*)  d_in[0];
    const int*   char_idxs = (const int*)  d_in[1];
    const int*   char_lens = (const int*)  d_in[2];
    const float* char_emb  = (const float*)d_in[3];
    const float* word_emb  = (const float*)d_in[4];
    const float* Wih_c     = (const float*)d_in[5];
    const float* Whh_c     = (const float*)d_in[6];
    const float* bih_c     = (const float*)d_in[7];
    const float* bhh_c     = (const float*)d_in[8];
    const float* Wih_w     = (const float*)d_in[9];
    const float* Whh_w     = (const float*)d_in[10];
    const float* bih_w     = (const float*)d_in[11];
    const float* bhh_w     = (const float*)d_in[12];
    float* out = (float*)d_out;

    const int char_smem = (CWPB * CE + CWPB * GC) * (int)sizeof(float);      // 81920 B
    const int wl_smem   = (32 * KW + 2 * HDIM + 4 * KW) * (int)sizeof(float); // 118784 B
    cudaFuncSetAttribute(char_lstm, cudaFuncAttributeMaxDynamicSharedMemorySize, char_smem);
    cudaFuncSetAttribute(word_lstm, cudaFuncAttributeMaxDynamicSharedMemorySize, wl_smem);

    prep_c<<<(2 * CE * GC + 255) / 256, 256>>>(Wih_c, Whh_c);
    prep_cg<<<ALPHA, 256>>>(char_emb, bih_c, bhh_c);   // needs g_WcT (same stream)
    prep_tags<<<8, 256>>>();

    char_lstm<<<S_WORDS / CWPB, 512, char_smem>>>(char_idxs, char_lens);

    word_lstm<<<NBLK_WL, 256, wl_smem>>>(word_idxs, word_emb, Wih_w, bih_w, bhh_w, Whh_w, out);
}

// round 14
// speedup vs baseline: 1.1613x; 1.1613x over previous
#include <cuda_runtime.h>
#include <cuda_bf16.h>
#include <math.h>

#define S_WORDS 2048
#define LMAX    16
#define CE      256
#define WE      512
#define HDIM    1024
#define GC      (4*CE)     // 1024 gate rows, char LSTM
#define GW      (4*HDIM)   // 4096 gate rows, word LSTM
#define KW      (WE+CE)    // 768  (we | char_feat)
#define ALPHA   256
#define NBLK_WL 128        // persistent blocks for word LSTM (<= 148 SMs)
#define CWPB    14         // words per block, char LSTM (147 blocks cover 2048 w/ clamp)
#define NCBLK   147
#define GWPB    16         // words per block, word gemm

typedef unsigned long long ull;

// ---------------- device scratch (no allocations allowed) ----------------
__device__ float g_WcT[2*CE*GC];      // [k=512][g=1024]; rows 0..255 = Wih_c^T, 256.. = Whh_c^T
__device__ float g_CG[ALPHA*GC];      // per-char x-gate table: emb@Wih^T + bias
__device__ float g_WihwT[KW*GW];      // [k=768][g=4096] transposed word input weights
__device__ float g_lasth[S_WORDS*CE]; // char-LSTM output feature per word
__device__ float g_GXw[S_WORDS*GW];   // precomputed x-part of word-LSTM gates (+bias)
// tagged h broadcast: high 32 bits = step tag, low 32 bits = h bits. Double-buffered.
__device__ ull g_hpair[2*HDIM];

__device__ __forceinline__ float sigf(float x) { return 1.f / (1.f + __expf(-x)); }
__device__ __forceinline__ float f2lo(ull v) { return __uint_as_float((unsigned)v); }
__device__ __forceinline__ float f2hi(ull v) { return __uint_as_float((unsigned)(v >> 32)); }
__device__ __forceinline__ void fma2(ull& acc, ull a, ull b) {
    asm("fma.rn.f32x2 %0, %1, %2, %0;" : "+l"(acc) : "l"(a), "l"(b));
}

// ---------------- prep: transposes, CG table, tag reset ----------------
__global__ void prep_c(const float* __restrict__ Wih_c, const float* __restrict__ Whh_c) {
    int idx = blockIdx.x * blockDim.x + threadIdx.x;
    if (idx >= 2 * CE * GC) return;
    int k = idx / GC, g = idx % GC;
    g_WcT[idx] = (k < CE) ? Wih_c[g * CE + k] : Whh_c[g * CE + (k - CE)];
}

__global__ void __launch_bounds__(256) prep_cg(const float* __restrict__ char_emb,
                                               const float* __restrict__ bih_c,
                                               const float* __restrict__ bhh_c) {
    __shared__ float se[CE];
    const int ci  = blockIdx.x;
    const int tid = threadIdx.x;
    se[tid] = char_emb[ci * CE + tid];
    __syncthreads();

    float4 acc = make_float4(bih_c[4*tid+0] + bhh_c[4*tid+0],
                             bih_c[4*tid+1] + bhh_c[4*tid+1],
                             bih_c[4*tid+2] + bhh_c[4*tid+2],
                             bih_c[4*tid+3] + bhh_c[4*tid+3]);
    const float4* Wp = reinterpret_cast<const float4*>(g_WcT) + tid;   // Wih^T half
#pragma unroll 4
    for (int k = 0; k < CE; k++) {
        float4 wv = Wp[k * (GC / 4)];
        float ev = se[k];
        acc.x = fmaf(wv.x, ev, acc.x);
        acc.y = fmaf(wv.y, ev, acc.y);
        acc.z = fmaf(wv.z, ev, acc.z);
        acc.w = fmaf(wv.w, ev, acc.w);
    }
    reinterpret_cast<float4*>(g_CG + ci * GC)[tid] = acc;
}

__global__ void prep_w(const float* __restrict__ Wih_w) {
    int idx = blockIdx.x * blockDim.x + threadIdx.x;
    if (idx < 2 * HDIM) g_hpair[idx] = 0xFFFFFFFF00000000ull;   // tag = -1
    if (idx >= KW * GW) return;
    int k = idx / GW, g = idx % GW;
    g_WihwT[idx] = Wih_w[g * KW + k];
}

// ---------------- char LSTM: 14 words/block, 147 blocks, 512 threads ----------------
// Out-of-range words in the last block clamp to word 2047 (duplicate identical work).
__global__ void __launch_bounds__(512) char_lstm(
    const int*   __restrict__ char_idxs,
    const int*   __restrict__ char_lens)
{
    extern __shared__ float sm[];
    float* hh    = sm;                // CWPB*256
    float* gates = sm + CWPB * CE;    // CWPB*1024
    const int tid   = threadIdx.x;      // 0..511
    const int wbase = blockIdx.x * CWPB;
    const int unit  = tid & 255;
    const int wgrp  = (tid >> 8) * 7;   // 7 words per half

    int weff[CWPB];
#pragma unroll
    for (int w = 0; w < CWPB; w++) {
        int g = wbase + w;
        weff[w] = (g < S_WORDS) ? g : (S_WORDS - 1);
    }

    float c[7];
    int   len[7];
#pragma unroll
    for (int j = 0; j < 7; j++) {
        int w = wgrp + j;
        c[j]   = 0.f;
        len[j] = char_lens[weff[w]];
        hh[w * CE + unit] = 0.f;
    }
    __syncthreads();

    const float2* Wp  = reinterpret_cast<const float2*>(g_WcT + (size_t)CE * GC) + tid;
    const float2* CG2 = reinterpret_cast<const float2*>(g_CG);

    for (int t = 0; t < LMAX; t++) {
        float acc[CWPB][2];
#pragma unroll
        for (int w = 0; w < CWPB; w++) {
            int ci = char_idxs[weff[w] * LMAX + t];
            float2 cg = CG2[ci * (GC / 2) + tid];
            acc[w][0] = cg.x; acc[w][1] = cg.y;
        }

#pragma unroll 4
        for (int k = 0; k < CE; k++) {
            float2 wv = Wp[k * (GC / 2)];
#pragma unroll
            for (int w = 0; w < CWPB; w++) {
                float xv = hh[w * CE + k];
                acc[w][0] = fmaf(wv.x, xv, acc[w][0]);
                acc[w][1] = fmaf(wv.y, xv, acc[w][1]);
            }
        }
#pragma unroll
        for (int w = 0; w < CWPB; w++)
            reinterpret_cast<float2*>(gates + w * GC)[tid] = make_float2(acc[w][0], acc[w][1]);
        __syncthreads();

#pragma unroll
        for (int j = 0; j < 7; j++) {
            int w = wgrp + j;
            float ig = gates[w * GC +          unit];
            float fg = gates[w * GC +   CE +   unit];
            float gg = gates[w * GC + 2*CE +   unit];
            float og = gates[w * GC + 3*CE +   unit];
            float cn = sigf(fg) * c[j] + sigf(ig) * tanhf(gg);
            float hn = sigf(og) * tanhf(cn);
            c[j] = cn;
            hh[w * CE + unit] = hn;
            if (t == len[j] - 1) g_lasth[weff[w] * CE + unit] = hn;  // dup stores = same value
        }
        __syncthreads();
    }
}

// ---------------- word-LSTM input GEMM: 16 words/block (R12, unchanged) ----------------
__global__ void __launch_bounds__(256) word_gemm(
    const int*   __restrict__ word_idxs,
    const float* __restrict__ word_emb,
    const float* __restrict__ bih_w,
    const float* __restrict__ bhh_w)
{
    extern __shared__ float xw[];   // [16][768]
    const int tid   = threadIdx.x;           // 0..255
    const int wbase = blockIdx.x * GWPB;
    const int gq    = blockIdx.y * 256 + tid; // float4 column index 0..1023

#pragma unroll
    for (int w = 0; w < GWPB; w++) {
        int wi = word_idxs[wbase + w];
        xw[w * KW +       tid] = word_emb[wi * WE +       tid];
        xw[w * KW + 256 + tid] = word_emb[wi * WE + 256 + tid];
        xw[w * KW + 512 + tid] = g_lasth[(wbase + w) * CE + tid];
    }
    __syncthreads();

    const int gbase = 4 * gq;
    float bias[4];
#pragma unroll
    for (int q = 0; q < 4; q++) bias[q] = bih_w[gbase + q] + bhh_w[gbase + q];

    float acc[GWPB][4];
#pragma unroll
    for (int w = 0; w < GWPB; w++)
#pragma unroll
        for (int q = 0; q < 4; q++) acc[w][q] = 0.f;

    const float4* Wp = reinterpret_cast<const float4*>(g_WihwT) + gq;
#pragma unroll 2
    for (int k = 0; k < KW; k++) {
        float4 wv = Wp[k * (GW / 4)];
#pragma unroll
        for (int w = 0; w < GWPB; w++) {
            float xv = xw[w * KW + k];
            acc[w][0] = fmaf(wv.x, xv, acc[w][0]);
            acc[w][1] = fmaf(wv.y, xv, acc[w][1]);
            acc[w][2] = fmaf(wv.z, xv, acc[w][2]);
            acc[w][3] = fmaf(wv.w, xv, acc[w][3]);
        }
    }
#pragma unroll
    for (int w = 0; w < GWPB; w++) {
        reinterpret_cast<float4*>(g_GXw + (size_t)(wbase + w) * GW)[gq] =
            make_float4(acc[w][0] + bias[0], acc[w][1] + bias[1],
                        acc[w][2] + bias[2], acc[w][3] + bias[3]);
    }
}

// ---------------- word LSTM recurrence: tagged-data sync + f32x2 FMA ----------------
__global__ void __launch_bounds__(256, 1) word_lstm(const float* __restrict__ Whh_w,
                                                    float*       __restrict__ out)
{
    __shared__ __align__(16) float hs[2][HDIM];
    const int tid  = threadIdx.x;
    const int lane = tid & 31;
    const int y    = tid >> 5;
    const int u    = blockIdx.x * 8 + y;

    // weight k-pairs: wq[i] covers h elements {2*(i*32+lane), +1}
    ull w0[16], w1[16], w2[16], w3[16];
    {
        const ull* W0 = reinterpret_cast<const ull*>(Whh_w + (size_t)(0*HDIM + u) * HDIM);
        const ull* W1 = reinterpret_cast<const ull*>(Whh_w + (size_t)(1*HDIM + u) * HDIM);
        const ull* W2 = reinterpret_cast<const ull*>(Whh_w + (size_t)(2*HDIM + u) * HDIM);
        const ull* W3 = reinterpret_cast<const ull*>(Whh_w + (size_t)(3*HDIM + u) * HDIM);
#pragma unroll
        for (int i = 0; i < 16; i++) {
            w0[i] = W0[i*32 + lane];
            w1[i] = W1[i*32 + lane];
            w2[i] = W2[i*32 + lane];
            w3[i] = W3[i*32 + lane];
        }
    }
    float c = 0.f;

    for (int s = 0; s < S_WORDS; s++) {
        const float* gx = g_GXw + (size_t)s * GW;
        float gi0 = gx[u];
        float gf0 = gx[HDIM     + u];
        float gg0 = gx[2*HDIM   + u];
        float go0 = gx[3*HDIM   + u];

        float s0 = 0.f, s1 = 0.f, s2 = 0.f, s3 = 0.f;
        if (s > 0) {
            const int want = s - 1;
            const int slot = want & 1;
            const ull* base = g_hpair + slot * HDIM + tid;

            ull v0, v1, v2, v3;
            unsigned done = 0;
            int rounds = 0;
            do {
                if (!(done & 1u))
                    asm volatile("ld.relaxed.gpu.global.b64 %0, [%1];" : "=l"(v0) : "l"(base));
                if (!(done & 2u))
                    asm volatile("ld.relaxed.gpu.global.b64 %0, [%1];" : "=l"(v1) : "l"(base + 256));
                if (!(done & 4u))
                    asm volatile("ld.relaxed.gpu.global.b64 %0, [%1];" : "=l"(v2) : "l"(base + 512));
                if (!(done & 8u))
                    asm volatile("ld.relaxed.gpu.global.b64 %0, [%1];" : "=l"(v3) : "l"(base + 768));
                if ((int)(v0 >> 32) == want) done |= 1u;
                if ((int)(v1 >> 32) == want) done |= 2u;
                if ((int)(v2 >> 32) == want) done |= 4u;
                if ((int)(v3 >> 32) == want) done |= 8u;
                if (done == 15u) break;
                if (++rounds > 16) __nanosleep(64);   // safety valve only
            } while (true);

            hs[slot][tid      ] = __uint_as_float((unsigned)v0);
            hs[slot][tid + 256] = __uint_as_float((unsigned)v1);
            hs[slot][tid + 512] = __uint_as_float((unsigned)v2);
            hs[slot][tid + 768] = __uint_as_float((unsigned)v3);
            __syncthreads();

            ull a0 = 0ull, a1 = 0ull, a2 = 0ull, a3 = 0ull;
            const ull* hp = reinterpret_cast<const ull*>(hs[slot]);
#pragma unroll
            for (int i = 0; i < 16; i++) {
                ull hv = hp[i * 32 + lane];
                fma2(a0, w0[i], hv);
                fma2(a1, w1[i], hv);
                fma2(a2, w2[i], hv);
                fma2(a3, w3[i], hv);
            }
            s0 = f2lo(a0) + f2hi(a0);
            s1 = f2lo(a1) + f2hi(a1);
            s2 = f2lo(a2) + f2hi(a2);
            s3 = f2lo(a3) + f2hi(a3);
        }
#pragma unroll
        for (int off = 16; off > 0; off >>= 1) {
            s0 += __shfl_xor_sync(0xffffffffu, s0, off);
            s1 += __shfl_xor_sync(0xffffffffu, s1, off);
            s2 += __shfl_xor_sync(0xffffffffu, s2, off);
            s3 += __shfl_xor_sync(0xffffffffu, s3, off);
        }

        float cn = sigf(gf0 + s1) * c + sigf(gi0 + s0) * tanhf(gg0 + s2);
        c = cn;
        float h = sigf(go0 + s3) * tanhf(cn);

        if (lane == 0) {
            out[(size_t)s * HDIM + u] = h;
            if (s < S_WORDS - 1) {
                ull pv = ((ull)(unsigned)s << 32) | (ull)__float_as_uint(h);
                const ull* ap = g_hpair + (s & 1) * HDIM + u;
                asm volatile("st.relaxed.gpu.global.b64 [%0], %1;" :: "l"(ap), "l"(pv) : "memory");
            }
        }
    }
}

// ---------------- launch ----------------
extern "C" void kernel_launch(void* const* d_in, const int* in_sizes, int n_in,
                              void* d_out, int out_size)
{
    const int*   word_idxs = (const int*)  d_in[0];
    const int*   char_idxs = (const int*)  d_in[1];
    const int*   char_lens = (const int*)  d_in[2];
    const float* char_emb  = (const float*)d_in[3];
    const float* word_emb  = (const float*)d_in[4];
    const float* Wih_c     = (const float*)d_in[5];
    const float* Whh_c     = (const float*)d_in[6];
    const float* bih_c     = (const float*)d_in[7];
    const float* bhh_c     = (const float*)d_in[8];
    const float* Wih_w     = (const float*)d_in[9];
    const float* Whh_w     = (const float*)d_in[10];
    const float* bih_w     = (const float*)d_in[11];
    const float* bhh_w     = (const float*)d_in[12];
    float* out = (float*)d_out;

    const int char_smem = (CWPB * CE + CWPB * GC) * (int)sizeof(float);  // 71680 B
    const int gemm_smem = GWPB * KW * (int)sizeof(float);                // 49152 B
    cudaFuncSetAttribute(char_lstm, cudaFuncAttributeMaxDynamicSharedMemorySize, char_smem);
    cudaFuncSetAttribute(word_gemm, cudaFuncAttributeMaxDynamicSharedMemorySize, gemm_smem);

    prep_c<<<(2 * CE * GC + 255) / 256, 256>>>(Wih_c, Whh_c);
    prep_cg<<<ALPHA, 256>>>(char_emb, bih_c, bhh_c);        // needs g_WcT (same stream)
    prep_w<<<(KW * GW + 255) / 256, 256>>>(Wih_w);          // also resets g_hpair tags

    char_lstm<<<NCBLK, 512, char_smem>>>(char_idxs, char_lens);

    word_gemm<<<dim3(S_WORDS / GWPB, 4), 256, gemm_smem>>>(word_idxs, word_emb, bih_w, bhh_w);

    word_lstm<<<NBLK_WL, 256>>>(Whh_w, out);
}

// round 15
// speedup vs baseline: 1.2871x; 1.1084x over previous
#include <cuda_runtime.h>
#include <cuda_bf16.h>
#include <math.h>

#define S_WORDS 2048
#define LMAX    16
#define CE      256
#define WE      512
#define HDIM    1024
#define GC      (4*CE)     // 1024 gate rows, char LSTM
#define GW      (4*HDIM)   // 4096 gate rows, word LSTM
#define KW      (WE+CE)    // 768  (we | char_feat)
#define ALPHA   256
#define NBLK_WL 128        // persistent blocks for word LSTM (<= 148 SMs)
#define CWPB    14         // words per block, char LSTM (147 blocks cover 2048 w/ clamp)
#define NCBLK   147
#define GWPB    16         // words per block, word gemm

// ---------------- device scratch (no allocations allowed) ----------------
__device__ float g_WcT[2*CE*GC];      // [k=512][g=1024]; rows 0..255 = Wih_c^T, 256.. = Whh_c^T
__device__ float g_CG[ALPHA*GC];      // per-char x-gate table: emb@Wih^T + bias
__device__ float g_WihwT[KW*GW];      // [k=768][g=4096] transposed word input weights
__device__ float g_lasth[S_WORDS*CE]; // char-LSTM output feature per word
__device__ float g_GXw[S_WORDS*GW];   // precomputed x-part of word-LSTM gates (+bias)
// tagged h broadcast: high 32 bits = step tag, low 32 bits = h bits. Double-buffered.
__device__ unsigned long long g_hpair[2*HDIM];

__device__ __forceinline__ float sigf(float x) { return 1.f / (1.f + __expf(-x)); }

// ---------------- prep: transposes, CG table, tag reset ----------------
__global__ void prep_c(const float* __restrict__ Wih_c, const float* __restrict__ Whh_c) {
    int idx = blockIdx.x * blockDim.x + threadIdx.x;
    if (idx >= 2 * CE * GC) return;
    int k = idx / GC, g = idx % GC;
    g_WcT[idx] = (k < CE) ? Wih_c[g * CE + k] : Whh_c[g * CE + (k - CE)];
}

__global__ void __launch_bounds__(256) prep_cg(const float* __restrict__ char_emb,
                                               const float* __restrict__ bih_c,
                                               const float* __restrict__ bhh_c) {
    __shared__ float se[CE];
    const int ci  = blockIdx.x;
    const int tid = threadIdx.x;
    se[tid] = char_emb[ci * CE + tid];
    __syncthreads();

    float4 acc = make_float4(bih_c[4*tid+0] + bhh_c[4*tid+0],
                             bih_c[4*tid+1] + bhh_c[4*tid+1],
                             bih_c[4*tid+2] + bhh_c[4*tid+2],
                             bih_c[4*tid+3] + bhh_c[4*tid+3]);
    const float4* Wp = reinterpret_cast<const float4*>(g_WcT) + tid;   // Wih^T half
#pragma unroll 4
    for (int k = 0; k < CE; k++) {
        float4 wv = Wp[k * (GC / 4)];
        float ev = se[k];
        acc.x = fmaf(wv.x, ev, acc.x);
        acc.y = fmaf(wv.y, ev, acc.y);
        acc.z = fmaf(wv.z, ev, acc.z);
        acc.w = fmaf(wv.w, ev, acc.w);
    }
    reinterpret_cast<float4*>(g_CG + ci * GC)[tid] = acc;
}

__global__ void prep_w(const float* __restrict__ Wih_w) {
    int idx = blockIdx.x * blockDim.x + threadIdx.x;
    if (idx < 2 * HDIM) g_hpair[idx] = 0xFFFFFFFF00000000ull;   // tag = -1
    if (idx >= KW * GW) return;
    int k = idx / GW, g = idx % GW;
    g_WihwT[idx] = Wih_w[g * KW + k];
}

// ---------------- char LSTM: 14 words/block, 147 blocks, 512 threads (R14 winner) ----------------
__global__ void __launch_bounds__(512) char_lstm(
    const int*   __restrict__ char_idxs,
    const int*   __restrict__ char_lens)
{
    extern __shared__ float sm[];
    float* hh    = sm;                // CWPB*256
    float* gates = sm + CWPB * CE;    // CWPB*1024
    const int tid   = threadIdx.x;      // 0..511
    const int wbase = blockIdx.x * CWPB;
    const int unit  = tid & 255;
    const int wgrp  = (tid >> 8) * 7;   // 7 words per half

    int weff[CWPB];
#pragma unroll
    for (int w = 0; w < CWPB; w++) {
        int g = wbase + w;
        weff[w] = (g < S_WORDS) ? g : (S_WORDS - 1);
    }

    float c[7];
    int   len[7];
#pragma unroll
    for (int j = 0; j < 7; j++) {
        int w = wgrp + j;
        c[j]   = 0.f;
        len[j] = char_lens[weff[w]];
        hh[w * CE + unit] = 0.f;
    }
    __syncthreads();

    const float2* Wp  = reinterpret_cast<const float2*>(g_WcT + (size_t)CE * GC) + tid;
    const float2* CG2 = reinterpret_cast<const float2*>(g_CG);

    for (int t = 0; t < LMAX; t++) {
        float acc[CWPB][2];
#pragma unroll
        for (int w = 0; w < CWPB; w++) {
            int ci = char_idxs[weff[w] * LMAX + t];
            float2 cg = CG2[ci * (GC / 2) + tid];
            acc[w][0] = cg.x; acc[w][1] = cg.y;
        }

#pragma unroll 4
        for (int k = 0; k < CE; k++) {
            float2 wv = Wp[k * (GC / 2)];
#pragma unroll
            for (int w = 0; w < CWPB; w++) {
                float xv = hh[w * CE + k];
                acc[w][0] = fmaf(wv.x, xv, acc[w][0]);
                acc[w][1] = fmaf(wv.y, xv, acc[w][1]);
            }
        }
#pragma unroll
        for (int w = 0; w < CWPB; w++)
            reinterpret_cast<float2*>(gates + w * GC)[tid] = make_float2(acc[w][0], acc[w][1]);
        __syncthreads();

#pragma unroll
        for (int j = 0; j < 7; j++) {
            int w = wgrp + j;
            float ig = gates[w * GC +          unit];
            float fg = gates[w * GC +   CE +   unit];
            float gg = gates[w * GC + 2*CE +   unit];
            float og = gates[w * GC + 3*CE +   unit];
            float cn = sigf(fg) * c[j] + sigf(ig) * tanhf(gg);
            float hn = sigf(og) * tanhf(cn);
            c[j] = cn;
            hh[w * CE + unit] = hn;
            if (t == len[j] - 1) g_lasth[weff[w] * CE + unit] = hn;  // dup stores = same value
        }
        __syncthreads();
    }
}

// ---------------- word-LSTM input GEMM: 16 words/block (R12, unchanged) ----------------
__global__ void __launch_bounds__(256) word_gemm(
    const int*   __restrict__ word_idxs,
    const float* __restrict__ word_emb,
    const float* __restrict__ bih_w,
    const float* __restrict__ bhh_w)
{
    extern __shared__ float xw[];   // [16][768]
    const int tid   = threadIdx.x;           // 0..255
    const int wbase = blockIdx.x * GWPB;
    const int gq    = blockIdx.y * 256 + tid; // float4 column index 0..1023

#pragma unroll
    for (int w = 0; w < GWPB; w++) {
        int wi = word_idxs[wbase + w];
        xw[w * KW +       tid] = word_emb[wi * WE +       tid];
        xw[w * KW + 256 + tid] = word_emb[wi * WE + 256 + tid];
        xw[w * KW + 512 + tid] = g_lasth[(wbase + w) * CE + tid];
    }
    __syncthreads();

    const int gbase = 4 * gq;
    float bias[4];
#pragma unroll
    for (int q = 0; q < 4; q++) bias[q] = bih_w[gbase + q] + bhh_w[gbase + q];

    float acc[GWPB][4];
#pragma unroll
    for (int w = 0; w < GWPB; w++)
#pragma unroll
        for (int q = 0; q < 4; q++) acc[w][q] = 0.f;

    const float4* Wp = reinterpret_cast<const float4*>(g_WihwT) + gq;
#pragma unroll 2
    for (int k = 0; k < KW; k++) {
        float4 wv = Wp[k * (GW / 4)];
#pragma unroll
        for (int w = 0; w < GWPB; w++) {
            float xv = xw[w * KW + k];
            acc[w][0] = fmaf(wv.x, xv, acc[w][0]);
            acc[w][1] = fmaf(wv.y, xv, acc[w][1]);
            acc[w][2] = fmaf(wv.z, xv, acc[w][2]);
            acc[w][3] = fmaf(wv.w, xv, acc[w][3]);
        }
    }
#pragma unroll
    for (int w = 0; w < GWPB; w++) {
        reinterpret_cast<float4*>(g_GXw + (size_t)(wbase + w) * GW)[gq] =
            make_float4(acc[w][0] + bias[0], acc[w][1] + bias[1],
                        acc[w][2] + bias[2], acc[w][3] + bias[3]);
    }
}

// ---------------- word LSTM recurrence: tagged-data sync, scalar FMA (R12 winner) ----------------
__global__ void __launch_bounds__(256, 1) word_lstm(const float* __restrict__ Whh_w,
                                                    float*       __restrict__ out)
{
    __shared__ float hs[2][HDIM];
    const int tid  = threadIdx.x;
    const int lane = tid & 31;
    const int y    = tid >> 5;
    const int u    = blockIdx.x * 8 + y;

    float w0[32], w1[32], w2[32], w3[32];
#pragma unroll
    for (int i = 0; i < 32; i++) {
        w0[i] = Whh_w[(size_t)(0 * HDIM + u) * HDIM + i * 32 + lane];
        w1[i] = Whh_w[(size_t)(1 * HDIM + u) * HDIM + i * 32 + lane];
        w2[i] = Whh_w[(size_t)(2 * HDIM + u) * HDIM + i * 32 + lane];
        w3[i] = Whh_w[(size_t)(3 * HDIM + u) * HDIM + i * 32 + lane];
    }
    float c = 0.f;

    for (int s = 0; s < S_WORDS; s++) {
        const float* gx = g_GXw + (size_t)s * GW;
        float gi0 = gx[u];
        float gf0 = gx[HDIM     + u];
        float gg0 = gx[2*HDIM   + u];
        float go0 = gx[3*HDIM   + u];

        float a0 = 0.f, a1 = 0.f, a2 = 0.f, a3 = 0.f;
        if (s > 0) {
            const int want = s - 1;
            const int slot = want & 1;
            const unsigned long long* base = g_hpair + slot * HDIM + tid;

            unsigned long long v0, v1, v2, v3;
            unsigned done = 0;
            int rounds = 0;
            do {
                if (!(done & 1u))
                    asm volatile("ld.relaxed.gpu.global.b64 %0, [%1];" : "=l"(v0) : "l"(base));
                if (!(done & 2u))
                    asm volatile("ld.relaxed.gpu.global.b64 %0, [%1];" : "=l"(v1) : "l"(base + 256));
                if (!(done & 4u))
                    asm volatile("ld.relaxed.gpu.global.b64 %0, [%1];" : "=l"(v2) : "l"(base + 512));
                if (!(done & 8u))
                    asm volatile("ld.relaxed.gpu.global.b64 %0, [%1];" : "=l"(v3) : "l"(base + 768));
                if ((int)(v0 >> 32) == want) done |= 1u;
                if ((int)(v1 >> 32) == want) done |= 2u;
                if ((int)(v2 >> 32) == want) done |= 4u;
                if ((int)(v3 >> 32) == want) done |= 8u;
                if (done == 15u) break;
                if (++rounds > 16) __nanosleep(64);   // safety valve only
            } while (true);

            hs[slot][tid      ] = __uint_as_float((unsigned)v0);
            hs[slot][tid + 256] = __uint_as_float((unsigned)v1);
            hs[slot][tid + 512] = __uint_as_float((unsigned)v2);
            hs[slot][tid + 768] = __uint_as_float((unsigned)v3);
            __syncthreads();

#pragma unroll
            for (int i = 0; i < 32; i++) {
                float hv = hs[slot][i * 32 + lane];
                a0 = fmaf(w0[i], hv, a0);
                a1 = fmaf(w1[i], hv, a1);
                a2 = fmaf(w2[i], hv, a2);
                a3 = fmaf(w3[i], hv, a3);
            }
        }
#pragma unroll
        for (int off = 16; off > 0; off >>= 1) {
            a0 += __shfl_xor_sync(0xffffffffu, a0, off);
            a1 += __shfl_xor_sync(0xffffffffu, a1, off);
            a2 += __shfl_xor_sync(0xffffffffu, a2, off);
            a3 += __shfl_xor_sync(0xffffffffu, a3, off);
        }

        float cn = sigf(gf0 + a1) * c + sigf(gi0 + a0) * tanhf(gg0 + a2);
        c = cn;
        float h = sigf(go0 + a3) * tanhf(cn);

        if (lane == 0) {
            out[(size_t)s * HDIM + u] = h;
            if (s < S_WORDS - 1) {
                unsigned long long pv =
                    ((unsigned long long)(unsigned)s << 32) | (unsigned long long)__float_as_uint(h);
                const unsigned long long* ap = g_hpair + (s & 1) * HDIM + u;
                asm volatile("st.relaxed.gpu.global.b64 [%0], %1;" :: "l"(ap), "l"(pv) : "memory");
            }
        }
    }
}

// ---------------- launch ----------------
extern "C" void kernel_launch(void* const* d_in, const int* in_sizes, int n_in,
                              void* d_out, int out_size)
{
    const int*   word_idxs = (const int*)  d_in[0];
    const int*   char_idxs = (const int*)  d_in[1];
    const int*   char_lens = (const int*)  d_in[2];
    const float* char_emb  = (const float*)d_in[3];
    const float* word_emb  = (const float*)d_in[4];
    const float* Wih_c     = (const float*)d_in[5];
    const float* Whh_c     = (const float*)d_in[6];
    const float* bih_c     = (const float*)d_in[7];
    const float* bhh_c     = (const float*)d_in[8];
    const float* Wih_w     = (const float*)d_in[9];
    const float* Whh_w     = (const float*)d_in[10];
    const float* bih_w     = (const float*)d_in[11];
    const float* bhh_w     = (const float*)d_in[12];
    float* out = (float*)d_out;

    const int char_smem = (CWPB * CE + CWPB * GC) * (int)sizeof(float);  // 71680 B
    const int gemm_smem = GWPB * KW * (int)sizeof(float);                // 49152 B
    cudaFuncSetAttribute(char_lstm, cudaFuncAttributeMaxDynamicSharedMemorySize, char_smem);
    cudaFuncSetAttribute(word_gemm, cudaFuncAttributeMaxDynamicSharedMemorySize, gemm_smem);

    prep_c<<<(2 * CE * GC + 255) / 256, 256>>>(Wih_c, Whh_c);
    prep_cg<<<ALPHA, 256>>>(char_emb, bih_c, bhh_c);        // needs g_WcT (same stream)
    prep_w<<<(KW * GW + 255) / 256, 256>>>(Wih_w);          // also resets g_hpair tags

    char_lstm<<<NCBLK, 512, char_smem>>>(char_idxs, char_lens);

    word_gemm<<<dim3(S_WORDS / GWPB, 4), 256, gemm_smem>>>(word_idxs, word_emb, bih_w, bhh_w);

    word_lstm<<<NBLK_WL, 256>>>(Whh_w, out);
}